// round 16
// baseline (speedup 1.0000x reference)
#include <cuda_runtime.h>
#include <cuda_bf16.h>
#include <math.h>
#include <stdint.h>

#define B_ 4
#define T_ 2048
#define C_ 1024
#define NH_ 16
#define HD_ 64
#define M_ (B_*T_)   // 8192

// Scratch (no allocations allowed).
__device__ float    g_q[(size_t)B_*NH_*T_*HD_];        // Q in [B,NH,T,HD] (float)
__device__ uint32_t g_op[(size_t)M_*C_];               // attn out, tf32 bits, A-frag layout
__device__ uint32_t g_xp[(size_t)M_*C_];               // x, tf32 bits, A-frag layout
__device__ uint32_t g_wqkvp[(size_t)C_*3*C_];          // W_qkv, tf32 bits, B-frag layout
__device__ uint32_t g_woutp[(size_t)C_*C_];            // W_out, tf32 bits, B-frag layout

__device__ __forceinline__ uint32_t f2tf32(float f) {
    uint32_t u;
    asm("cvt.rna.tf32.f32 %0, %1;" : "=r"(u) : "f"(f));
    return u;
}

__device__ __forceinline__ void cp16(void* smem_dst, const void* gmem_src) {
    uint32_t s = (uint32_t)__cvta_generic_to_shared(smem_dst);
    asm volatile("cp.async.cg.shared.global [%0], [%1], 16;" :: "r"(s), "l"(gmem_src));
}

__device__ __forceinline__ void mma_tf32(float* cc, const uint32_t* a,
                                         uint32_t b0, uint32_t b1) {
    asm volatile(
        "mma.sync.aligned.m16n8k8.row.col.f32.tf32.tf32.f32 "
        "{%0,%1,%2,%3}, {%4,%5,%6,%7}, {%8,%9}, {%0,%1,%2,%3};"
        : "+f"(cc[0]), "+f"(cc[1]), "+f"(cc[2]), "+f"(cc[3])
        : "r"(a[0]), "r"(a[1]), "r"(a[2]), "r"(a[3]), "r"(b0), "r"(b1));
}

// ---------------------------------------------------------------------------
// Pre-pass: convert fp32 -> tf32 bits, permute into mma fragment order.
// ---------------------------------------------------------------------------
__global__ void permA(const float* __restrict__ src, uint32_t* __restrict__ dst,
                      int Mrows, int Kdim) {
    int Ktiles = Kdim >> 3;
    size_t total4 = (size_t)Mrows * Kdim / 4;
    for (size_t i4 = (size_t)blockIdx.x * blockDim.x + threadIdx.x; i4 < total4;
         i4 += (size_t)gridDim.x * blockDim.x) {
        size_t idx = i4 * 4;
        int m = (int)(idx / Kdim), k = (int)(idx % Kdim);   // k % 4 == 0
        float4 v = *(const float4*)(src + idx);
        size_t base = ((size_t)(m >> 4) * Ktiles + (k >> 3)) * 128;
        int e = ((k >> 2) & 1) * 2 + ((m >> 3) & 1);
        int l0 = (m & 7) * 4;
        dst[base + (l0 + 0) * 4 + e] = f2tf32(v.x);
        dst[base + (l0 + 1) * 4 + e] = f2tf32(v.y);
        dst[base + (l0 + 2) * 4 + e] = f2tf32(v.z);
        dst[base + (l0 + 3) * 4 + e] = f2tf32(v.w);
    }
}

__global__ void permB(const float* __restrict__ src, uint32_t* __restrict__ dst,
                      int Kdim, int N) {
    int Ktiles = Kdim >> 3;
    size_t total4 = (size_t)Kdim * N / 4;
    for (size_t i4 = (size_t)blockIdx.x * blockDim.x + threadIdx.x; i4 < total4;
         i4 += (size_t)gridDim.x * blockDim.x) {
        size_t idx = i4 * 4;
        int k = (int)(idx / N), n = (int)(idx % N);          // n % 4 == 0
        float4 v = *(const float4*)(src + idx);
        size_t base = ((size_t)(n >> 3) * Ktiles + (k >> 3)) * 64;
        int e = (k >> 2) & 1;
        int kc = k & 3;
        dst[base + (((n & 7) + 0) * 4 + kc) * 2 + e] = f2tf32(v.x);
        dst[base + (((n & 7) + 1) * 4 + kc) * 2 + e] = f2tf32(v.y);
        dst[base + (((n & 7) + 2) * 4 + kc) * 2 + e] = f2tf32(v.z);
        dst[base + (((n & 7) + 3) * 4 + kc) * 2 + e] = f2tf32(v.w);
    }
}

// ---------------------------------------------------------------------------
// GEMM mainloop: 3-stage cp.async pipeline, one __syncthreads per k-iter.
// (verified: qkv 266us)
// ---------------------------------------------------------------------------
#define STAGE_U32 8192
#define SMEM_BYTES (3*STAGE_U32*4)     // 98304

__device__ __forceinline__ void gemm_mainloop_p(
    const uint32_t* __restrict__ Ap, const uint32_t* __restrict__ Bp,
    int Ktiles, int m0, int n0, uint32_t* sm, float acc[2][8][4])
{
    const int tid = threadIdx.x, lane = tid & 31, warp = tid >> 5;
    const int mt0 = (warp & 3) * 2;
    const int ntb = (warp >> 2) * 8;
    const int ITERS = Ktiles / 4;

    auto issue_load = [&](int stage, int kt0) {
        uint32_t* As = sm + stage * STAGE_U32;
        uint32_t* Bs = As + 4096;
#pragma unroll
        for (int i = 0; i < 4; ++i) {
            int idx = tid + i * 256;
            int ach = idx >> 7, au = idx & 127;
            cp16(As + ach * 512 + au * 4,
                 Ap + (((size_t)((m0 >> 4) + ach) * Ktiles + kt0) * 128) + au * 4);
            int bch = idx >> 6, bu = idx & 63;
            cp16(Bs + bch * 256 + bu * 4,
                 Bp + (((size_t)((n0 >> 3) + bch) * Ktiles + kt0) * 64) + bu * 4);
        }
        asm volatile("cp.async.commit_group;");
    };

    issue_load(0, 0);
    issue_load(1, 4);

    for (int it = 0; it < ITERS; ++it) {
        if (it + 2 < ITERS) {
            asm volatile("cp.async.wait_group 1;");
        } else {
            asm volatile("cp.async.wait_group 0;");
        }
        __syncthreads();
        if (it + 2 < ITERS) issue_load((it + 2) % 3, (it + 2) * 4);

        const uint32_t* as = sm + (it % 3) * STAGE_U32;
        const uint32_t* bs = as + 4096;
#pragma unroll
        for (int ks = 0; ks < 4; ++ks) {
            uint4 a0 = *(const uint4*)&as[((mt0 + 0) * 4 + ks) * 128 + lane * 4];
            uint4 a1 = *(const uint4*)&as[((mt0 + 1) * 4 + ks) * 128 + lane * 4];
#pragma unroll
            for (int nt = 0; nt < 8; ++nt) {
                uint2 b = *(const uint2*)&bs[((ntb + nt) * 4 + ks) * 64 + lane * 2];
                mma_tf32(acc[0][nt], (const uint32_t*)&a0, b.x, b.y);
                mma_tf32(acc[1][nt], (const uint32_t*)&a1, b.x, b.y);
            }
        }
    }
    __syncthreads();
}

// ---------------------------------------------------------------------------
// QKV GEMM: g_xp[M,C] @ g_wqkvp[C,3C] + b, scatter epilogue (q/k/v split).
// ---------------------------------------------------------------------------
__global__ __launch_bounds__(256) void qkv_gemm(const float* __restrict__ bias,
                                                float* __restrict__ outK,
                                                float* __restrict__ outV) {
    extern __shared__ uint32_t sm[];
    int m0 = blockIdx.y * 128, n0 = blockIdx.x * 128;
    float acc[2][8][4];
#pragma unroll
    for (int i = 0; i < 2; ++i)
#pragma unroll
        for (int j = 0; j < 8; ++j)
#pragma unroll
            for (int p = 0; p < 4; ++p) acc[i][j][p] = 0.f;

    gemm_mainloop_p(g_xp, g_wqkvp, C_ / 8, m0, n0, sm, acc);

    const int lane = threadIdx.x & 31, warp = threadIdx.x >> 5;
    const int r = lane >> 2, c = lane & 3;
    const int mb = (warp & 3) * 32, nb = (warp >> 2) * 64;

#pragma unroll
    for (int mt = 0; mt < 2; ++mt) {
#pragma unroll
        for (int nt = 0; nt < 8; ++nt) {
            int n = n0 + nb + nt * 8 + 2 * c;
            float bx = bias[n], by = bias[n + 1];
            int region = n >> 10;
            int cc = n & (C_ - 1);
            int h = cc >> 6, d = cc & 63;
            float* dstbase = (region == 0) ? g_q : (region == 1) ? outK : outV;
#pragma unroll
            for (int half = 0; half < 2; ++half) {
                int m = m0 + mb + mt * 16 + r + half * 8;
                int bb = m >> 11, t = m & (T_ - 1);
                size_t dst = ((size_t)(bb * NH_ + h) * T_ + t) * HD_ + d;
                float2 v2;
                v2.x = acc[mt][nt][half * 2 + 0] + bx;
                v2.y = acc[mt][nt][half * 2 + 1] + by;
                *(float2*)(dstbase + dst) = v2;
            }
        }
    }
}

// ---------------------------------------------------------------------------
// Output projection: g_op[M,C] @ g_woutp[C,C] + b_out -> y
// ---------------------------------------------------------------------------
__global__ __launch_bounds__(256) void out_gemm(const float* __restrict__ bias,
                                                float* __restrict__ Y) {
    extern __shared__ uint32_t sm[];
    int m0 = blockIdx.y * 128, n0 = blockIdx.x * 128;
    float acc[2][8][4];
#pragma unroll
    for (int i = 0; i < 2; ++i)
#pragma unroll
        for (int j = 0; j < 8; ++j)
#pragma unroll
            for (int p = 0; p < 4; ++p) acc[i][j][p] = 0.f;

    gemm_mainloop_p(g_op, g_woutp, C_ / 8, m0, n0, sm, acc);

    const int lane = threadIdx.x & 31, warp = threadIdx.x >> 5;
    const int r = lane >> 2, c = lane & 3;
    const int mb = (warp & 3) * 32, nb = (warp >> 2) * 64;

#pragma unroll
    for (int mt = 0; mt < 2; ++mt) {
#pragma unroll
        for (int nt = 0; nt < 8; ++nt) {
            int n = n0 + nb + nt * 8 + 2 * c;
            float bx = bias[n], by = bias[n + 1];
#pragma unroll
            for (int half = 0; half < 2; ++half) {
                int m = m0 + mb + mt * 16 + r + half * 8;
                float2 v2;
                v2.x = acc[mt][nt][half * 2 + 0] + bx;
                v2.y = acc[mt][nt][half * 2 + 1] + by;
                *(float2*)(Y + (size_t)m * C_ + n) = v2;
            }
        }
    }
}

// ---------------------------------------------------------------------------
// Tensor-core flash attention — R12-proven version (BM=64, 4 warps,
// padded-stride smem, uint4 conflict-free staging, cvt at staging).
// ---------------------------------------------------------------------------
#define KS_STRIDE 68
#define VS_STRIDE 72
#define PS_STRIDE 68
#define ATT_SMEM_FLOATS (64*KS_STRIDE + 64*VS_STRIDE + 64*PS_STRIDE)
#define ATT_SMEM_BYTES (ATT_SMEM_FLOATS*4)   // 53248

__global__ __launch_bounds__(128) void attn_tc(const float* __restrict__ gk,
                                               const float* __restrict__ gv) {
    extern __shared__ uint32_t smu[];
    uint32_t* Ks = smu;
    uint32_t* Vs = Ks + 64 * KS_STRIDE;
    uint32_t* Ps = Vs + 64 * VS_STRIDE;

    const int bh = blockIdx.y;
    const int q0 = blockIdx.x * 64;
    const int tid = threadIdx.x, lane = tid & 31, warp = tid >> 5;
    const int r = lane >> 2, c = lane & 3;

    const float* qbase = g_q + (size_t)bh * T_ * HD_;
    const float* kbase = gk + (size_t)bh * T_ * HD_;
    const float* vbase = gv + (size_t)bh * T_ * HD_;

    const int qrow0 = q0 + warp * 16;
    uint32_t qf[8][4];
#pragma unroll
    for (int kg = 0; kg < 8; ++kg) {
        qf[kg][0] = f2tf32(qbase[(size_t)(qrow0 + r)     * HD_ + kg * 8 + c]     * 0.125f);
        qf[kg][1] = f2tf32(qbase[(size_t)(qrow0 + r + 8) * HD_ + kg * 8 + c]     * 0.125f);
        qf[kg][2] = f2tf32(qbase[(size_t)(qrow0 + r)     * HD_ + kg * 8 + c + 4] * 0.125f);
        qf[kg][3] = f2tf32(qbase[(size_t)(qrow0 + r + 8) * HD_ + kg * 8 + c + 4] * 0.125f);
    }

    float acc_o[8][4];
#pragma unroll
    for (int i = 0; i < 8; ++i)
#pragma unroll
        for (int j = 0; j < 4; ++j) acc_o[i][j] = 0.f;
    float m0v = -INFINITY, m1v = -INFINITY, l0 = 0.f, l1 = 0.f;

    const int ntiles = q0 / 64 + 1;
    for (int t = 0; t < ntiles; ++t) {
        const int j0 = t * 64;
        __syncthreads();
        for (int i = tid; i < 64 * 16; i += 128) {
            int row = i >> 4, c4 = (i & 15) * 4;
            float4 kk = *(const float4*)(kbase + (size_t)(j0 + row) * HD_ + c4);
            float4 vv = *(const float4*)(vbase + (size_t)(j0 + row) * HD_ + c4);
            uint4 ku = make_uint4(f2tf32(kk.x), f2tf32(kk.y), f2tf32(kk.z), f2tf32(kk.w));
            uint4 vu = make_uint4(f2tf32(vv.x), f2tf32(vv.y), f2tf32(vv.z), f2tf32(vv.w));
            *(uint4*)&Ks[row * KS_STRIDE + c4] = ku;
            *(uint4*)&Vs[row * VS_STRIDE + c4] = vu;
        }
        __syncthreads();

        float accs[8][4];
#pragma unroll
        for (int i = 0; i < 8; ++i)
#pragma unroll
            for (int j = 0; j < 4; ++j) accs[i][j] = 0.f;
#pragma unroll
        for (int kg = 0; kg < 8; ++kg) {
#pragma unroll
            for (int nt = 0; nt < 8; ++nt) {
                uint32_t b0 = Ks[(nt * 8 + r) * KS_STRIDE + kg * 8 + c];
                uint32_t b1 = Ks[(nt * 8 + r) * KS_STRIDE + kg * 8 + c + 4];
                mma_tf32(accs[nt], qf[kg], b0, b1);
            }
        }

        if (j0 + 63 > qrow0) {
#pragma unroll
            for (int nt = 0; nt < 8; ++nt) {
#pragma unroll
                for (int e = 0; e < 4; ++e) {
                    int j = j0 + nt * 8 + 2 * c + (e & 1);
                    int q = qrow0 + r + 8 * (e >> 1);
                    if (j > q) accs[nt][e] = -INFINITY;
                }
            }
        }

        float mt0 = -INFINITY, mt1 = -INFINITY;
#pragma unroll
        for (int nt = 0; nt < 8; ++nt) {
            mt0 = fmaxf(mt0, fmaxf(accs[nt][0], accs[nt][1]));
            mt1 = fmaxf(mt1, fmaxf(accs[nt][2], accs[nt][3]));
        }
        mt0 = fmaxf(mt0, __shfl_xor_sync(0xffffffffu, mt0, 1));
        mt0 = fmaxf(mt0, __shfl_xor_sync(0xffffffffu, mt0, 2));
        mt1 = fmaxf(mt1, __shfl_xor_sync(0xffffffffu, mt1, 1));
        mt1 = fmaxf(mt1, __shfl_xor_sync(0xffffffffu, mt1, 2));
        float mn0 = fmaxf(m0v, mt0), mn1 = fmaxf(m1v, mt1);
        float sc0 = __expf(m0v - mn0), sc1 = __expf(m1v - mn1);

        float ps0 = 0.f, ps1 = 0.f;
#pragma unroll
        for (int nt = 0; nt < 8; ++nt) {
            float p0 = __expf(accs[nt][0] - mn0);
            float p1 = __expf(accs[nt][1] - mn0);
            float p2 = __expf(accs[nt][2] - mn1);
            float p3 = __expf(accs[nt][3] - mn1);
            ps0 += p0 + p1; ps1 += p2 + p3;
            int col = nt * 8 + 2 * c;
            Ps[(warp * 16 + r)     * PS_STRIDE + col]     = f2tf32(p0);
            Ps[(warp * 16 + r)     * PS_STRIDE + col + 1] = f2tf32(p1);
            Ps[(warp * 16 + r + 8) * PS_STRIDE + col]     = f2tf32(p2);
            Ps[(warp * 16 + r + 8) * PS_STRIDE + col + 1] = f2tf32(p3);
        }
        ps0 += __shfl_xor_sync(0xffffffffu, ps0, 1);
        ps0 += __shfl_xor_sync(0xffffffffu, ps0, 2);
        ps1 += __shfl_xor_sync(0xffffffffu, ps1, 1);
        ps1 += __shfl_xor_sync(0xffffffffu, ps1, 2);
        l0 = l0 * sc0 + ps0;
        l1 = l1 * sc1 + ps1;
        m0v = mn0; m1v = mn1;
#pragma unroll
        for (int nt = 0; nt < 8; ++nt) {
            acc_o[nt][0] *= sc0; acc_o[nt][1] *= sc0;
            acc_o[nt][2] *= sc1; acc_o[nt][3] *= sc1;
        }
        __syncwarp();

#pragma unroll
        for (int kg = 0; kg < 8; ++kg) {
            uint32_t a[4];
            a[0] = Ps[(warp * 16 + r)     * PS_STRIDE + kg * 8 + c];
            a[1] = Ps[(warp * 16 + r + 8) * PS_STRIDE + kg * 8 + c];
            a[2] = Ps[(warp * 16 + r)     * PS_STRIDE + kg * 8 + c + 4];
            a[3] = Ps[(warp * 16 + r + 8) * PS_STRIDE + kg * 8 + c + 4];
#pragma unroll
            for (int nt = 0; nt < 8; ++nt) {
                uint32_t b0 = Vs[(kg * 8 + c)     * VS_STRIDE + nt * 8 + r];
                uint32_t b1 = Vs[(kg * 8 + c + 4) * VS_STRIDE + nt * 8 + r];
                mma_tf32(acc_o[nt], a, b0, b1);
            }
        }
        __syncwarp();
    }

    // Epilogue: write g_op in A-fragment tf32-bit layout.
    const int b = bh >> 4, h = bh & 15;
    float inv0 = 1.f / l0, inv1 = 1.f / l1;
    const int mtile = b * (T_ / 16) + (qrow0 >> 4);
    const int Ktiles = C_ / 8;
#pragma unroll
    for (int nt = 0; nt < 8; ++nt) {
        size_t base = ((size_t)mtile * Ktiles + (h * 8 + nt)) * 128;
        int kc0 = 2 * c;
        int kc1 = 2 * c + 1;
        int off00 = (r * 4 + (kc0 & 3)) * 4 + ((kc0 >> 2) & 1) * 2;
        int off01 = (r * 4 + (kc1 & 3)) * 4 + ((kc1 >> 2) & 1) * 2;
        g_op[base + off00]     = f2tf32(acc_o[nt][0] * inv0);
        g_op[base + off01]     = f2tf32(acc_o[nt][1] * inv0);
        g_op[base + off00 + 1] = f2tf32(acc_o[nt][2] * inv1);
        g_op[base + off01 + 1] = f2tf32(acc_o[nt][3] * inv1);
    }
}

// ---------------------------------------------------------------------------
extern "C" void kernel_launch(void* const* d_in, const int* in_sizes, int n_in,
                              void* d_out, int out_size) {
    const float* x    = (const float*)d_in[0];
    const float* Wqkv = (const float*)d_in[1];
    const float* bqkv = (const float*)d_in[2];
    const float* Wout = (const float*)d_in[3];
    const float* bout = (const float*)d_in[4];

    float* y = (float*)d_out;
    float* k = y + (size_t)B_ * T_ * C_;
    float* v = k + (size_t)B_ * T_ * C_;

    static int configured = 0;
    if (!configured) {
        cudaFuncSetAttribute((const void*)qkv_gemm,
                             cudaFuncAttributeMaxDynamicSharedMemorySize, SMEM_BYTES);
        cudaFuncSetAttribute((const void*)out_gemm,
                             cudaFuncAttributeMaxDynamicSharedMemorySize, SMEM_BYTES);
        cudaFuncSetAttribute((const void*)attn_tc,
                             cudaFuncAttributeMaxDynamicSharedMemorySize, ATT_SMEM_BYTES);
        configured = 1;
    }

    uint32_t* xp; uint32_t* wqkvp; uint32_t* woutp;
    cudaGetSymbolAddress((void**)&xp, g_xp);
    cudaGetSymbolAddress((void**)&wqkvp, g_wqkvp);
    cudaGetSymbolAddress((void**)&woutp, g_woutp);

    permA<<<1024, 256>>>(x, xp, M_, C_);
    permB<<<1024, 256>>>(Wqkv, wqkvp, C_, 3 * C_);
    permB<<<512, 256>>>(Wout, woutp, C_, C_);

    qkv_gemm<<<dim3(3 * C_ / 128, M_ / 128), 256, SMEM_BYTES>>>(bqkv, k, v);
    attn_tc<<<dim3(T_ / 64, B_ * NH_), 128, ATT_SMEM_BYTES>>>(k, v);
    out_gemm<<<dim3(C_ / 128, M_ / 128), 256, SMEM_BYTES>>>(bout, y);
}

// round 17
// speedup vs baseline: 1.5879x; 1.5879x over previous
#include <cuda_runtime.h>
#include <cuda_bf16.h>
#include <math.h>
#include <stdint.h>

#define B_ 4
#define T_ 2048
#define C_ 1024
#define NH_ 16
#define HD_ 64
#define M_ (B_*T_)   // 8192

// Scratch (no allocations allowed).
__device__ float    g_q[(size_t)B_*NH_*T_*HD_];        // Q in [B,NH,T,HD] (float)
__device__ uint32_t g_op[(size_t)M_*C_];               // attn out, tf32 bits, A-frag layout
__device__ uint32_t g_xp[(size_t)M_*C_];               // x, tf32 bits, A-frag layout
__device__ uint32_t g_wqkvp[(size_t)C_*3*C_];          // W_qkv, tf32 bits, B-frag layout
__device__ uint32_t g_woutp[(size_t)C_*C_];            // W_out, tf32 bits, B-frag layout
__device__ uint32_t g_kp[(size_t)B_*NH_*T_*HD_];       // K, tf32 bits, B-frag (n=key,k=dim)
__device__ uint32_t g_vp[(size_t)B_*NH_*T_*HD_];       // V, tf32 bits, B-frag (n=dim,k=key)

__device__ __forceinline__ uint32_t f2tf32(float f) {
    uint32_t u;
    asm("cvt.rna.tf32.f32 %0, %1;" : "=r"(u) : "f"(f));
    return u;
}

__device__ __forceinline__ void cp16(void* smem_dst, const void* gmem_src) {
    uint32_t s = (uint32_t)__cvta_generic_to_shared(smem_dst);
    asm volatile("cp.async.cg.shared.global [%0], [%1], 16;" :: "r"(s), "l"(gmem_src));
}

__device__ __forceinline__ void mma_tf32(float* cc, const uint32_t* a,
                                         uint32_t b0, uint32_t b1) {
    asm volatile(
        "mma.sync.aligned.m16n8k8.row.col.f32.tf32.tf32.f32 "
        "{%0,%1,%2,%3}, {%4,%5,%6,%7}, {%8,%9}, {%0,%1,%2,%3};"
        : "+f"(cc[0]), "+f"(cc[1]), "+f"(cc[2]), "+f"(cc[3])
        : "r"(a[0]), "r"(a[1]), "r"(a[2]), "r"(a[3]), "r"(b0), "r"(b1));
}

// ---------------------------------------------------------------------------
// Pre-pass: convert fp32 -> tf32 bits, permute into mma fragment order.
// ---------------------------------------------------------------------------
__global__ void permA(const float* __restrict__ src, uint32_t* __restrict__ dst,
                      int Mrows, int Kdim) {
    int Ktiles = Kdim >> 3;
    size_t total4 = (size_t)Mrows * Kdim / 4;
    for (size_t i4 = (size_t)blockIdx.x * blockDim.x + threadIdx.x; i4 < total4;
         i4 += (size_t)gridDim.x * blockDim.x) {
        size_t idx = i4 * 4;
        int m = (int)(idx / Kdim), k = (int)(idx % Kdim);   // k % 4 == 0
        float4 v = *(const float4*)(src + idx);
        size_t base = ((size_t)(m >> 4) * Ktiles + (k >> 3)) * 128;
        int e = ((k >> 2) & 1) * 2 + ((m >> 3) & 1);
        int l0 = (m & 7) * 4;
        dst[base + (l0 + 0) * 4 + e] = f2tf32(v.x);
        dst[base + (l0 + 1) * 4 + e] = f2tf32(v.y);
        dst[base + (l0 + 2) * 4 + e] = f2tf32(v.z);
        dst[base + (l0 + 3) * 4 + e] = f2tf32(v.w);
    }
}

__global__ void permB(const float* __restrict__ src, uint32_t* __restrict__ dst,
                      int Kdim, int N) {
    int Ktiles = Kdim >> 3;
    size_t total4 = (size_t)Kdim * N / 4;
    for (size_t i4 = (size_t)blockIdx.x * blockDim.x + threadIdx.x; i4 < total4;
         i4 += (size_t)gridDim.x * blockDim.x) {
        size_t idx = i4 * 4;
        int k = (int)(idx / N), n = (int)(idx % N);          // n % 4 == 0
        float4 v = *(const float4*)(src + idx);
        size_t base = ((size_t)(n >> 3) * Ktiles + (k >> 3)) * 64;
        int e = (k >> 2) & 1;
        int kc = k & 3;
        dst[base + (((n & 7) + 0) * 4 + kc) * 2 + e] = f2tf32(v.x);
        dst[base + (((n & 7) + 1) * 4 + kc) * 2 + e] = f2tf32(v.y);
        dst[base + (((n & 7) + 2) * 4 + kc) * 2 + e] = f2tf32(v.z);
        dst[base + (((n & 7) + 3) * 4 + kc) * 2 + e] = f2tf32(v.w);
    }
}

// ---------------------------------------------------------------------------
// GEMM mainloop: 3-stage cp.async pipeline, one __syncthreads per k-iter.
// ---------------------------------------------------------------------------
#define STAGE_U32 8192
#define SMEM_BYTES (3*STAGE_U32*4)     // 98304

__device__ __forceinline__ void gemm_mainloop_p(
    const uint32_t* __restrict__ Ap, const uint32_t* __restrict__ Bp,
    int Ktiles, int m0, int n0, uint32_t* sm, float acc[2][8][4])
{
    const int tid = threadIdx.x, lane = tid & 31, warp = tid >> 5;
    const int mt0 = (warp & 3) * 2;
    const int ntb = (warp >> 2) * 8;
    const int ITERS = Ktiles / 4;

    auto issue_load = [&](int stage, int kt0) {
        uint32_t* As = sm + stage * STAGE_U32;
        uint32_t* Bs = As + 4096;
#pragma unroll
        for (int i = 0; i < 4; ++i) {
            int idx = tid + i * 256;
            int ach = idx >> 7, au = idx & 127;
            cp16(As + ach * 512 + au * 4,
                 Ap + (((size_t)((m0 >> 4) + ach) * Ktiles + kt0) * 128) + au * 4);
            int bch = idx >> 6, bu = idx & 63;
            cp16(Bs + bch * 256 + bu * 4,
                 Bp + (((size_t)((n0 >> 3) + bch) * Ktiles + kt0) * 64) + bu * 4);
        }
        asm volatile("cp.async.commit_group;");
    };

    issue_load(0, 0);
    issue_load(1, 4);

    for (int it = 0; it < ITERS; ++it) {
        if (it + 2 < ITERS) {
            asm volatile("cp.async.wait_group 1;");
        } else {
            asm volatile("cp.async.wait_group 0;");
        }
        __syncthreads();
        if (it + 2 < ITERS) issue_load((it + 2) % 3, (it + 2) * 4);

        const uint32_t* as = sm + (it % 3) * STAGE_U32;
        const uint32_t* bs = as + 4096;
#pragma unroll
        for (int ks = 0; ks < 4; ++ks) {
            uint4 a0 = *(const uint4*)&as[((mt0 + 0) * 4 + ks) * 128 + lane * 4];
            uint4 a1 = *(const uint4*)&as[((mt0 + 1) * 4 + ks) * 128 + lane * 4];
#pragma unroll
            for (int nt = 0; nt < 8; ++nt) {
                uint2 b = *(const uint2*)&bs[((ntb + nt) * 4 + ks) * 64 + lane * 2];
                mma_tf32(acc[0][nt], (const uint32_t*)&a0, b.x, b.y);
                mma_tf32(acc[1][nt], (const uint32_t*)&a1, b.x, b.y);
            }
        }
    }
    __syncthreads();
}

// ---------------------------------------------------------------------------
// QKV GEMM: g_xp[M,C] @ g_wqkvp[C,3C] + b, scatter epilogue.
// Also writes K,V as tf32 bits in B-frag layouts (g_kp, g_vp) so attention
// can stage them with raw cp.async (no cvt, no shuffle).
// ---------------------------------------------------------------------------
__global__ __launch_bounds__(256) void qkv_gemm(const float* __restrict__ bias,
                                                float* __restrict__ outK,
                                                float* __restrict__ outV) {
    extern __shared__ uint32_t sm[];
    int m0 = blockIdx.y * 128, n0 = blockIdx.x * 128;
    float acc[2][8][4];
#pragma unroll
    for (int i = 0; i < 2; ++i)
#pragma unroll
        for (int j = 0; j < 8; ++j)
#pragma unroll
            for (int p = 0; p < 4; ++p) acc[i][j][p] = 0.f;

    gemm_mainloop_p(g_xp, g_wqkvp, C_ / 8, m0, n0, sm, acc);

    const int lane = threadIdx.x & 31, warp = threadIdx.x >> 5;
    const int r = lane >> 2, c = lane & 3;
    const int mb = (warp & 3) * 32, nb = (warp >> 2) * 64;

#pragma unroll
    for (int mt = 0; mt < 2; ++mt) {
#pragma unroll
        for (int nt = 0; nt < 8; ++nt) {
            int n = n0 + nb + nt * 8 + 2 * c;
            float bx = bias[n], by = bias[n + 1];
            int region = n >> 10;
            int cc = n & (C_ - 1);
            int h = cc >> 6, d = cc & 63;
            float* dstbase = (region == 0) ? g_q : (region == 1) ? outK : outV;
#pragma unroll
            for (int half = 0; half < 2; ++half) {
                int m = m0 + mb + mt * 16 + r + half * 8;
                int bb = m >> 11, t = m & (T_ - 1);
                int bh = bb * NH_ + h;
                size_t dst = ((size_t)bh * T_ + t) * HD_ + d;
                float2 v2;
                v2.x = acc[mt][nt][half * 2 + 0] + bx;
                v2.y = acc[mt][nt][half * 2 + 1] + by;
                *(float2*)(dstbase + dst) = v2;
                if (region == 1) {
                    // K B-frag (n=key=t, k=dim=d): [bh][t>>3][d>>3][64]
                    size_t tb = (((size_t)bh * (T_ / 8) + (t >> 3)) * 8 + (d >> 3)) * 64;
                    int e = (c >> 1) & 1;                  // (d>>2)&1 for d=2c,2c+1
                    int ko = (t & 7) * 4;
                    g_kp[tb + (ko + ((2 * c) & 3)) * 2 + e]     = f2tf32(v2.x);
                    g_kp[tb + (ko + ((2 * c + 1) & 3)) * 2 + e] = f2tf32(v2.y);
                } else if (region == 2) {
                    // V B-frag (n=dim=d, k=key=t): [bh][t>>3][d>>3][64]
                    size_t tb = (((size_t)bh * (T_ / 8) + (t >> 3)) * 8 + (d >> 3)) * 64;
                    int e = (t >> 2) & 1;
                    g_vp[tb + (((2 * c) & 7) * 4 + (t & 3)) * 2 + e]     = f2tf32(v2.x);
                    g_vp[tb + (((2 * c + 1) & 7) * 4 + (t & 3)) * 2 + e] = f2tf32(v2.y);
                }
            }
        }
    }
}

// ---------------------------------------------------------------------------
// Output projection: g_op[M,C] @ g_woutp[C,C] + b_out -> y
// ---------------------------------------------------------------------------
__global__ __launch_bounds__(256) void out_gemm(const float* __restrict__ bias,
                                                float* __restrict__ Y) {
    extern __shared__ uint32_t sm[];
    int m0 = blockIdx.y * 128, n0 = blockIdx.x * 128;
    float acc[2][8][4];
#pragma unroll
    for (int i = 0; i < 2; ++i)
#pragma unroll
        for (int j = 0; j < 8; ++j)
#pragma unroll
            for (int p = 0; p < 4; ++p) acc[i][j][p] = 0.f;

    gemm_mainloop_p(g_op, g_woutp, C_ / 8, m0, n0, sm, acc);

    const int lane = threadIdx.x & 31, warp = threadIdx.x >> 5;
    const int r = lane >> 2, c = lane & 3;
    const int mb = (warp & 3) * 32, nb = (warp >> 2) * 64;

#pragma unroll
    for (int mt = 0; mt < 2; ++mt) {
#pragma unroll
        for (int nt = 0; nt < 8; ++nt) {
            int n = n0 + nb + nt * 8 + 2 * c;
            float bx = bias[n], by = bias[n + 1];
#pragma unroll
            for (int half = 0; half < 2; ++half) {
                int m = m0 + mb + mt * 16 + r + half * 8;
                float2 v2;
                v2.x = acc[mt][nt][half * 2 + 0] + bx;
                v2.y = acc[mt][nt][half * 2 + 1] + by;
                *(float2*)(Y + (size_t)m * C_ + n) = v2;
            }
        }
    }
}

// ---------------------------------------------------------------------------
// Tensor-core flash attention, BM=64, 4 warps. K/V arrive PRE-FRAGMENTED
// (g_kp/g_vp) -> staging is pure cp.async of contiguous 16KB blocks,
// double-buffered across key tiles. All b-operand loads are LDS.64.
// P round-trips through smem (R12-proven layout). Bit-identical math to R12.
// ---------------------------------------------------------------------------
#define PS_STRIDE 68
#define KV_STAGE_U32 8192                       // Kb 4096 + Vb 4096
#define ATT_SMEM_U32 (2*KV_STAGE_U32 + 64*PS_STRIDE)
#define ATT_SMEM_BYTES (ATT_SMEM_U32*4)         // 82944

__global__ __launch_bounds__(128) void attn_tc(const uint32_t* __restrict__ gkp,
                                               const uint32_t* __restrict__ gvp) {
    extern __shared__ uint32_t smu[];
    uint32_t* Ps = smu + 2 * KV_STAGE_U32;

    const int bh = blockIdx.y;
    const int q0 = blockIdx.x * 64;
    const int tid = threadIdx.x, lane = tid & 31, warp = tid >> 5;
    const int r = lane >> 2, c = lane & 3;

    const float* qbase = g_q + (size_t)bh * T_ * HD_;
    const uint32_t* kpb = gkp + (size_t)bh * (T_ / 8) * 512;
    const uint32_t* vpb = gvp + (size_t)bh * (T_ / 8) * 512;

    const int qrow0 = q0 + warp * 16;
    uint32_t qf[8][4];
#pragma unroll
    for (int kg = 0; kg < 8; ++kg) {
        qf[kg][0] = f2tf32(qbase[(size_t)(qrow0 + r)     * HD_ + kg * 8 + c]     * 0.125f);
        qf[kg][1] = f2tf32(qbase[(size_t)(qrow0 + r + 8) * HD_ + kg * 8 + c]     * 0.125f);
        qf[kg][2] = f2tf32(qbase[(size_t)(qrow0 + r)     * HD_ + kg * 8 + c + 4] * 0.125f);
        qf[kg][3] = f2tf32(qbase[(size_t)(qrow0 + r + 8) * HD_ + kg * 8 + c + 4] * 0.125f);
    }

    float acc_o[8][4];
#pragma unroll
    for (int i = 0; i < 8; ++i)
#pragma unroll
        for (int j = 0; j < 4; ++j) acc_o[i][j] = 0.f;
    float m0v = -INFINITY, m1v = -INFINITY, l0 = 0.f, l1 = 0.f;

    const int ntiles = q0 / 64 + 1;

    auto issue_kv = [&](int stage, int tt) {
        uint32_t* Kb = smu + stage * KV_STAGE_U32;
        uint32_t* Vb = Kb + 4096;
        const uint32_t* ks = kpb + (size_t)(tt * 8) * 512;   // 8 keytiles * 512
        const uint32_t* vs = vpb + (size_t)(tt * 8) * 512;
#pragma unroll
        for (int i = 0; i < 8; ++i) {
            int u = tid * 4 + i * 512;
            cp16(Kb + u, ks + u);
            cp16(Vb + u, vs + u);
        }
        asm volatile("cp.async.commit_group;");
    };

    issue_kv(0, 0);

    for (int t = 0; t < ntiles; ++t) {
        const int j0 = t * 64;
        asm volatile("cp.async.wait_group 0;");
        __syncthreads();
        if (t + 1 < ntiles) issue_kv((t + 1) & 1, t + 1);

        const uint32_t* Kb = smu + (t & 1) * KV_STAGE_U32;
        const uint32_t* Vb = Kb + 4096;

        // S = (Q/8) K^T ; Kb tiles [keytile][dimtile][64], b-load LDS.64
        float accs[8][4];
#pragma unroll
        for (int i = 0; i < 8; ++i)
#pragma unroll
            for (int j = 0; j < 4; ++j) accs[i][j] = 0.f;
#pragma unroll
        for (int kg = 0; kg < 8; ++kg) {
#pragma unroll
            for (int nt = 0; nt < 8; ++nt) {
                uint2 b = *(const uint2*)&Kb[(nt * 8 + kg) * 64 + lane * 2];
                mma_tf32(accs[nt], qf[kg], b.x, b.y);
            }
        }

        if (j0 + 63 > qrow0) {
#pragma unroll
            for (int nt = 0; nt < 8; ++nt) {
#pragma unroll
                for (int e = 0; e < 4; ++e) {
                    int j = j0 + nt * 8 + 2 * c + (e & 1);
                    int q = qrow0 + r + 8 * (e >> 1);
                    if (j > q) accs[nt][e] = -INFINITY;
                }
            }
        }

        float mt0 = -INFINITY, mt1 = -INFINITY;
#pragma unroll
        for (int nt = 0; nt < 8; ++nt) {
            mt0 = fmaxf(mt0, fmaxf(accs[nt][0], accs[nt][1]));
            mt1 = fmaxf(mt1, fmaxf(accs[nt][2], accs[nt][3]));
        }
        mt0 = fmaxf(mt0, __shfl_xor_sync(0xffffffffu, mt0, 1));
        mt0 = fmaxf(mt0, __shfl_xor_sync(0xffffffffu, mt0, 2));
        mt1 = fmaxf(mt1, __shfl_xor_sync(0xffffffffu, mt1, 1));
        mt1 = fmaxf(mt1, __shfl_xor_sync(0xffffffffu, mt1, 2));
        float mn0 = fmaxf(m0v, mt0), mn1 = fmaxf(m1v, mt1);
        float sc0 = __expf(m0v - mn0), sc1 = __expf(m1v - mn1);

        float ps0 = 0.f, ps1 = 0.f;
#pragma unroll
        for (int nt = 0; nt < 8; ++nt) {
            float p0 = __expf(accs[nt][0] - mn0);
            float p1 = __expf(accs[nt][1] - mn0);
            float p2 = __expf(accs[nt][2] - mn1);
            float p3 = __expf(accs[nt][3] - mn1);
            ps0 += p0 + p1; ps1 += p2 + p3;
            int col = nt * 8 + 2 * c;
            Ps[(warp * 16 + r)     * PS_STRIDE + col]     = f2tf32(p0);
            Ps[(warp * 16 + r)     * PS_STRIDE + col + 1] = f2tf32(p1);
            Ps[(warp * 16 + r + 8) * PS_STRIDE + col]     = f2tf32(p2);
            Ps[(warp * 16 + r + 8) * PS_STRIDE + col + 1] = f2tf32(p3);
        }
        ps0 += __shfl_xor_sync(0xffffffffu, ps0, 1);
        ps0 += __shfl_xor_sync(0xffffffffu, ps0, 2);
        ps1 += __shfl_xor_sync(0xffffffffu, ps1, 1);
        ps1 += __shfl_xor_sync(0xffffffffu, ps1, 2);
        l0 = l0 * sc0 + ps0;
        l1 = l1 * sc1 + ps1;
        m0v = mn0; m1v = mn1;
#pragma unroll
        for (int nt = 0; nt < 8; ++nt) {
            acc_o[nt][0] *= sc0; acc_o[nt][1] *= sc0;
            acc_o[nt][2] *= sc1; acc_o[nt][3] *= sc1;
        }
        __syncwarp();

        // O += P V ; Vb tiles [keytile][dimtile][64], b-load LDS.64
#pragma unroll
        for (int kg = 0; kg < 8; ++kg) {
            uint32_t a[4];
            a[0] = Ps[(warp * 16 + r)     * PS_STRIDE + kg * 8 + c];
            a[1] = Ps[(warp * 16 + r + 8) * PS_STRIDE + kg * 8 + c];
            a[2] = Ps[(warp * 16 + r)     * PS_STRIDE + kg * 8 + c + 4];
            a[3] = Ps[(warp * 16 + r + 8) * PS_STRIDE + kg * 8 + c + 4];
#pragma unroll
            for (int nt = 0; nt < 8; ++nt) {
                uint2 b = *(const uint2*)&Vb[(kg * 8 + nt) * 64 + lane * 2];
                mma_tf32(acc_o[nt], a, b.x, b.y);
            }
        }
        __syncwarp();
    }

    // Epilogue: write g_op in A-fragment tf32-bit layout.
    const int b = bh >> 4, h = bh & 15;
    float inv0 = 1.f / l0, inv1 = 1.f / l1;
    const int mtile = b * (T_ / 16) + (qrow0 >> 4);
    const int Ktiles = C_ / 8;
#pragma unroll
    for (int nt = 0; nt < 8; ++nt) {
        size_t base = ((size_t)mtile * Ktiles + (h * 8 + nt)) * 128;
        int kc0 = 2 * c;
        int kc1 = 2 * c + 1;
        int off00 = (r * 4 + (kc0 & 3)) * 4 + ((kc0 >> 2) & 1) * 2;
        int off01 = (r * 4 + (kc1 & 3)) * 4 + ((kc1 >> 2) & 1) * 2;
        g_op[base + off00]     = f2tf32(acc_o[nt][0] * inv0);
        g_op[base + off01]     = f2tf32(acc_o[nt][1] * inv0);
        g_op[base + off00 + 1] = f2tf32(acc_o[nt][2] * inv1);
        g_op[base + off01 + 1] = f2tf32(acc_o[nt][3] * inv1);
    }
}

// ---------------------------------------------------------------------------
extern "C" void kernel_launch(void* const* d_in, const int* in_sizes, int n_in,
                              void* d_out, int out_size) {
    const float* x    = (const float*)d_in[0];
    const float* Wqkv = (const float*)d_in[1];
    const float* bqkv = (const float*)d_in[2];
    const float* Wout = (const float*)d_in[3];
    const float* bout = (const float*)d_in[4];

    float* y = (float*)d_out;
    float* k = y + (size_t)B_ * T_ * C_;
    float* v = k + (size_t)B_ * T_ * C_;

    static int configured = 0;
    if (!configured) {
        cudaFuncSetAttribute((const void*)qkv_gemm,
                             cudaFuncAttributeMaxDynamicSharedMemorySize, SMEM_BYTES);
        cudaFuncSetAttribute((const void*)out_gemm,
                             cudaFuncAttributeMaxDynamicSharedMemorySize, SMEM_BYTES);
        cudaFuncSetAttribute((const void*)attn_tc,
                             cudaFuncAttributeMaxDynamicSharedMemorySize, ATT_SMEM_BYTES);
        configured = 1;
    }

    uint32_t* xp; uint32_t* wqkvp; uint32_t* woutp; uint32_t* kp; uint32_t* vp;
    cudaGetSymbolAddress((void**)&xp, g_xp);
    cudaGetSymbolAddress((void**)&wqkvp, g_wqkvp);
    cudaGetSymbolAddress((void**)&woutp, g_woutp);
    cudaGetSymbolAddress((void**)&kp, g_kp);
    cudaGetSymbolAddress((void**)&vp, g_vp);

    permA<<<1024, 256>>>(x, xp, M_, C_);
    permB<<<1024, 256>>>(Wqkv, wqkvp, C_, 3 * C_);
    permB<<<512, 256>>>(Wout, woutp, C_, C_);

    qkv_gemm<<<dim3(3 * C_ / 128, M_ / 128), 256, SMEM_BYTES>>>(bqkv, k, v);
    attn_tc<<<dim3(T_ / 64, B_ * NH_), 128, ATT_SMEM_BYTES>>>(kp, vp);
    out_gemm<<<dim3(C_ / 128, M_ / 128), 256, SMEM_BYTES>>>(bout, y);
}